// round 5
// baseline (speedup 1.0000x reference)
#include <cuda_runtime.h>
#include <stdint.h>

#define TP   64
#define NTH  512
#define WDIM 128
#define HDIM 64
#define EXP  8
#define DXX  63
#define DVV  27
#define KK1  78       // padded k-pairs for W_r1 (155 -> 156)

typedef unsigned long long ull;

// ---- pre-packed weight scratch (k-pair interleaved) ----
__device__ float g_Wenc[32 * 128 * 2];           // [kp][c][2]  (k=63 zero-padded)
__device__ float g_Wsh [8 * 64 * 128 * 2];       // [e][kp][c][2]
__device__ float g_Wr1 [8 * KK1 * 64 * 2];       // [e][kp][c][2] (k=155 zero-padded)

// ---- shared memory layout (floats) ----
#define OFF_U    0                      // s_xyz [64][66] then s_shb [64][128]
#define OFF_VD   (OFF_U   + 64*128)     // [64][28]
#define OFF_Y    (OFF_VD  + 64*28)      // [64][128]; s_h [64][66] overlays after expert loop
#define OFF_SH   (OFF_Y   + 64*128)     // [64][132]
#define OFF_G    (OFF_SH  + 64*132)     // [64][8]
#define OFF_RED  (OFF_G   + 64*8)       // [4][64]
#define OFF_BSC  (OFF_RED + 64*4)
#define OFF_BSIG (OFF_BSC + 64)
#define OFF_BEXP (OFF_BSIG + 64)
#define OFF_UPD  (OFF_BEXP + 64)
#define SMEM_FLOATS (OFF_UPD + 64)      // 110592 B

__device__ __forceinline__ void ffma2(ull& acc, ull a, ull b) {
    asm("fma.rn.f32x2 %0, %1, %2, %0;" : "+l"(acc) : "l"(a), "l"(b));
}
__device__ __forceinline__ float2 unpack2(ull v) {
    float2 f; asm("mov.b64 {%0, %1}, %2;" : "=f"(f.x), "=f"(f.y) : "l"(v)); return f;
}

// ---- JAX threefry2x32 (20 rounds) ----
__device__ __forceinline__ uint2 tf2x32(unsigned k0, unsigned k1, unsigned x0, unsigned x1) {
    unsigned ks2 = k0 ^ k1 ^ 0x1BD11BDAu;
    x0 += k0; x1 += k1;
#define TFR(r) { x0 += x1; x1 = (x1 << (r)) | (x1 >> (32 - (r))); x1 ^= x0; }
    TFR(13) TFR(15) TFR(26) TFR(6)
    x0 += k1;  x1 += ks2 + 1u;
    TFR(17) TFR(29) TFR(16) TFR(24)
    x0 += ks2; x1 += k0 + 2u;
    TFR(13) TFR(15) TFR(26) TFR(6)
    x0 += k0;  x1 += k1 + 3u;
    TFR(17) TFR(29) TFR(16) TFR(24)
    x0 += k1;  x1 += ks2 + 4u;
    TFR(13) TFR(15) TFR(26) TFR(6)
    x0 += ks2; x1 += k0 + 5u;
#undef TFR
    return make_uint2(x0, x1);
}

// ---- prep: repack weights into k-pair-interleaved layouts ----
__global__ void prep_pack(const float* __restrict__ W_enc,
                          const float* __restrict__ W_sh,
                          const float* __restrict__ W_r1) {
    const int i = blockIdx.x * blockDim.x + threadIdx.x;
    if (i < 32 * 128 * 2) {
        const int j = i & 1, c = (i >> 1) & 127, kp = i >> 8;
        const int k = 2 * kp + j;
        g_Wenc[i] = (k < DXX) ? W_enc[k * 128 + c] : 0.f;
    }
    const int i2 = i - 32 * 128 * 2;
    if (i2 >= 0 && i2 < 8 * 64 * 128 * 2) {
        const int j = i2 & 1, c = (i2 >> 1) & 127, kp = (i2 >> 8) & 63, e = i2 >> 14;
        g_Wsh[i2] = W_sh[e * 16384 + (2 * kp + j) * 128 + c];
    }
    const int i3 = i - (32 * 128 * 2 + 8 * 64 * 128 * 2);
    if (i3 >= 0 && i3 < 8 * KK1 * 64 * 2) {
        const int e = i3 / (KK1 * 64 * 2), r = i3 % (KK1 * 64 * 2);
        const int kp = r >> 7, c = (r >> 1) & 63, j = r & 1;
        const int k = 2 * kp + j;
        g_Wr1[i3] = (k < 155) ? W_r1[e * 155 * 64 + k * 64 + c] : 0.f;
    }
}

__global__ void __launch_bounds__(NTH, 1)
nerf_fused(const float* __restrict__ x,
           const float* __restrict__ b_enc,
           const float* __restrict__ b_sh,
           const float* __restrict__ w_sig, const float* __restrict__ b_sig,
           const float* __restrict__ b_r1,
           const float* __restrict__ W_r2,  const float* __restrict__ b_r2,
           float* __restrict__ out, int n)
{
    extern __shared__ float sm[];
    const int tid = threadIdx.x;
    const int n0  = blockIdx.x * TP;

    float* s_xyz  = sm + OFF_U;      // stride 66 (Phase A/B only)
    float* s_shb  = sm + OFF_U;      // stride 128 (expert loop onward)
    float* s_vd   = sm + OFF_VD;     // stride 28
    float* s_y    = sm + OFF_Y;      // stride 128
    float* s_h    = sm + OFF_Y;      // stride 66 overlay (after expert loop)
    float* s_sh   = sm + OFF_SH;     // stride 132
    float* s_g    = sm + OFF_G;
    float* s_red  = sm + OFF_RED;
    float* s_bsc  = sm + OFF_BSC;
    float* s_bsig = sm + OFF_BSIG;
    float* s_bexp = sm + OFF_BEXP;
    float* s_upd  = sm + OFF_UPD;

    // ---------- Phase A: positional encodings ----------
    if (tid < 192) {
        const int p = tid / 3, c = tid % 3;
        float xc = 0.f, vc = 0.f;
        if (n0 + p < n) {
            xc = x[(n0 + p) * 6 + c];
            vc = x[(n0 + p) * 6 + 3 + c];
        }
        s_xyz[p * 66 + c] = xc;
        float f = 1.f;
#pragma unroll
        for (int i = 0; i < 10; i++) {
            float sv, cv; sincosf(f * xc, &sv, &cv);
            s_xyz[p * 66 + 3  + 3 * i + c] = sv;
            s_xyz[p * 66 + 33 + 3 * i + c] = cv;
            f *= 2.f;
        }
        s_vd[p * 28 + c] = vc;
        f = 1.f;
#pragma unroll
        for (int i = 0; i < 4; i++) {
            float sv, cv; sincosf(f * vc, &sv, &cv);
            s_vd[p * 28 + 3  + 3 * i + c] = sv;
            s_vd[p * 28 + 15 + 3 * i + c] = cv;
            f *= 2.f;
        }
        if (tid < 64) {
            s_xyz[tid * 66 + 63] = 0.f;   // zero pad for k-pair tail
            s_vd[tid * 28 + 27]  = 0.f;
        }
    }
    // ---------- Phase A2: Gumbel noise (JAX threefry, partitionable) ----------
    {
        const int idx = tid;                       // TP*EXP == NTH
        const int p = idx >> 3;
        const unsigned f = (unsigned)(n0 + p) * 8u + (unsigned)(idx & 7);
        const uint2 r = tf2x32(0u, 42u, 0u, f);
        const unsigned bits = r.x ^ r.y;
        const float u = __uint_as_float((bits >> 9) | 0x3f800000u) - 1.0f;
        s_g[idx] = -logf(-logf(u + 1e-20f) + 1e-20f);
    }
    __syncthreads();

    const int wp = tid >> 5, l = tid & 31, p0 = wp * 4;   // 16 warps x 4 points

    // ---------- Phase B: y = relu(xyz_pe @ W_enc + b_enc) ----------
    {
        ull acc[4][4];
#pragma unroll
        for (int p = 0; p < 4; p++)
#pragma unroll
            for (int c = 0; c < 4; c++) acc[p][c] = 0ull;
        const float* wb = g_Wenc + l * 8;
        const float* xb = s_xyz + p0 * 66;
#pragma unroll 2
        for (int kp = 0; kp < 32; kp++) {
            const ull* w01 = (const ull*)(wb + kp * 256);
            const ull pc0 = w01[0], pc1 = w01[1], pc2 = w01[2], pc3 = w01[3];
#pragma unroll
            for (int p = 0; p < 4; p++) {
                const ull a = *(const ull*)(xb + p * 66 + 2 * kp);
                ffma2(acc[p][0], a, pc0); ffma2(acc[p][1], a, pc1);
                ffma2(acc[p][2], a, pc2); ffma2(acc[p][3], a, pc3);
            }
        }
        const float4 bv = *(const float4*)(b_enc + l * 4);
#pragma unroll
        for (int p = 0; p < 4; p++) {
            const float2 f0 = unpack2(acc[p][0]), f1 = unpack2(acc[p][1]);
            const float2 f2 = unpack2(acc[p][2]), f3 = unpack2(acc[p][3]);
            float4 r4;
            r4.x = fmaxf(f0.x + f0.y + bv.x, 0.f);
            r4.y = fmaxf(f1.x + f1.y + bv.y, 0.f);
            r4.z = fmaxf(f2.x + f2.y + bv.z, 0.f);
            r4.w = fmaxf(f3.x + f3.y + bv.w, 0.f);
            *(float4*)(s_y + (p0 + p) * WDIM + l * 4) = r4;
        }
    }
    __syncthreads();

    // ---------- Expert loop: shape + sigma + gating; running-best copy ----------
    for (int e = 0; e < EXP; e++) {
        // C1: shape = relu(y @ W_sh[e] + b_sh[e])
        {
            ull acc[4][4];
#pragma unroll
            for (int p = 0; p < 4; p++)
#pragma unroll
                for (int c = 0; c < 4; c++) acc[p][c] = 0ull;
            const float* wb = g_Wsh + e * 16384 + l * 8;
            const float* yb = s_y + p0 * WDIM;
#pragma unroll 2
            for (int kp = 0; kp < 64; kp++) {
                const ull* w01 = (const ull*)(wb + kp * 256);
                const ull pc0 = w01[0], pc1 = w01[1], pc2 = w01[2], pc3 = w01[3];
#pragma unroll
                for (int p = 0; p < 4; p++) {
                    const ull a = *(const ull*)(yb + p * WDIM + 2 * kp);
                    ffma2(acc[p][0], a, pc0); ffma2(acc[p][1], a, pc1);
                    ffma2(acc[p][2], a, pc2); ffma2(acc[p][3], a, pc3);
                }
            }
            const float4 bv = *(const float4*)(b_sh + e * WDIM + l * 4);
#pragma unroll
            for (int p = 0; p < 4; p++) {
                const float2 f0 = unpack2(acc[p][0]), f1 = unpack2(acc[p][1]);
                const float2 f2 = unpack2(acc[p][2]), f3 = unpack2(acc[p][3]);
                float4 r4;
                r4.x = fmaxf(f0.x + f0.y + bv.x, 0.f);
                r4.y = fmaxf(f1.x + f1.y + bv.y, 0.f);
                r4.z = fmaxf(f2.x + f2.y + bv.z, 0.f);
                r4.w = fmaxf(f3.x + f3.y + bv.w, 0.f);
                *(float4*)(s_sh + (p0 + p) * 132 + l * 4) = r4;
            }
        }
        __syncthreads();

        // C2: sigma partials (4 threads/point, first 256 threads)
        if (tid < 256) {
            const int p = tid & 63, q = tid >> 6;
            const float* sp = s_sh + p * 132 + q * 32;
            const float* wq = w_sig + q * 32;
            float acc = 0.f;
#pragma unroll
            for (int i = 0; i < 8; i++) {
                const float4 sv = *(const float4*)(sp + i * 4);
                const float4 wv = *(const float4*)(wq + i * 4);
                acc = fmaf(sv.x, wv.x, acc); acc = fmaf(sv.y, wv.y, acc);
                acc = fmaf(sv.z, wv.z, acc); acc = fmaf(sv.w, wv.w, acc);
            }
            s_red[q * 64 + p] = acc;
        }
        __syncthreads();
        if (tid < 64) {
            const int p = tid;
            const float t = s_red[p] + s_red[64 + p] + s_red[128 + p] + s_red[192 + p] + b_sig[0];
            const float sg = fmaxf(t, 0.f) + log1pf(expf(-fabsf(t)));  // softplus
            const float sc = logf(sg + 1e-10f) / 0.166667f + s_g[p * 8 + e];
            const bool win = (e == 0) || (sc > s_bsc[p]);
            s_upd[p] = win ? 1.f : 0.f;
            if (win) {
                s_bsc[p]  = sc;
                s_bsig[p] = sg;
                s_bexp[p] = (float)e;
            }
        }
        __syncthreads();

        // copy newly-winning shape rows into s_shb
#pragma unroll
        for (int p = 0; p < 4; p++) {
            if (s_upd[p0 + p] != 0.f)
                *(float4*)(s_shb + (p0 + p) * 128 + l * 4) =
                    *(const float4*)(s_sh + (p0 + p) * 132 + l * 4);
        }
        __syncthreads();
    }

    // ---------- C3': h = relu([shb | vd] @ W_r1[winner] + b_r1[winner]) ----------
    {
        const float* w1p[4];
        ull acc[4][2];
#pragma unroll
        for (int p = 0; p < 4; p++) {
            const int we = (int)s_bexp[p0 + p];
            w1p[p] = g_Wr1 + we * (KK1 * 64 * 2) + l * 4;
            acc[p][0] = 0ull; acc[p][1] = 0ull;
        }
        const float* sb = s_shb + p0 * 128;
#pragma unroll 2
        for (int kp = 0; kp < 64; kp++) {
#pragma unroll
            for (int p = 0; p < 4; p++) {
                const float4 w4 = *(const float4*)(w1p[p] + kp * 128);
                const ull a = *(const ull*)(sb + p * 128 + 2 * kp);
                ffma2(acc[p][0], a, *(const ull*)&w4.x);
                ffma2(acc[p][1], a, *(const ull*)&w4.z);
            }
        }
        const float* vb = s_vd + p0 * 28;
#pragma unroll
        for (int kp = 64; kp < KK1; kp++) {
#pragma unroll
            for (int p = 0; p < 4; p++) {
                const float4 w4 = *(const float4*)(w1p[p] + kp * 128);
                const ull a = *(const ull*)(vb + p * 28 + 2 * (kp - 64));
                ffma2(acc[p][0], a, *(const ull*)&w4.x);
                ffma2(acc[p][1], a, *(const ull*)&w4.z);
            }
        }
#pragma unroll
        for (int p = 0; p < 4; p++) {
            const int we = (int)s_bexp[p0 + p];
            const float2 bv = *(const float2*)(b_r1 + we * HDIM + l * 2);
            const float2 f0 = unpack2(acc[p][0]), f1 = unpack2(acc[p][1]);
            float2 r2;
            r2.x = fmaxf(f0.x + f0.y + bv.x, 0.f);
            r2.y = fmaxf(f1.x + f1.y + bv.y, 0.f);
            *(float2*)(s_h + (p0 + p) * 66 + l * 2) = r2;
        }
    }
    __syncthreads();

    // ---------- C4': rgb = sigmoid(h @ W_r2[winner] + b_r2[winner]) → out ----------
    if (tid < 192) {
        const int p = tid % 64, c = tid / 64;
        const int we = (int)s_bexp[p];
        float acc = b_r2[we * 3 + c];
        const float* hp = s_h + p * 66;
        const float* w2 = W_r2 + we * HDIM * 3 + c;
#pragma unroll
        for (int k = 0; k < HDIM; k++) acc = fmaf(hp[k], w2[k * 3], acc);
        if (n0 + p < n)
            out[(n0 + p) * 4 + c] = 1.f / (1.f + expf(-acc));
    }
    if (tid < 64 && n0 + tid < n)
        out[(n0 + tid) * 4 + 3] = s_bsig[tid];
}

extern "C" void kernel_launch(void* const* d_in, const int* in_sizes, int n_in,
                              void* d_out, int out_size) {
    const float* x     = (const float*)d_in[0];
    const float* W_enc = (const float*)d_in[1];
    const float* b_enc = (const float*)d_in[2];
    const float* W_sh  = (const float*)d_in[3];
    const float* b_sh  = (const float*)d_in[4];
    const float* w_sig = (const float*)d_in[5];
    const float* b_sig = (const float*)d_in[6];
    const float* W_r1  = (const float*)d_in[7];
    const float* b_r1  = (const float*)d_in[8];
    const float* W_r2  = (const float*)d_in[9];
    const float* b_r2  = (const float*)d_in[10];
    float* out = (float*)d_out;

    const int n = in_sizes[0] / 6;
    const int blocks = (n + TP - 1) / TP;
    const int smem = SMEM_FLOATS * (int)sizeof(float);

    const int prep_elems = 32*128*2 + 8*64*128*2 + 8*KK1*64*2;
    prep_pack<<<(prep_elems + 255) / 256, 256>>>(W_enc, W_sh, W_r1);

    cudaFuncSetAttribute(nerf_fused, cudaFuncAttributeMaxDynamicSharedMemorySize, smem);
    nerf_fused<<<blocks, NTH, smem>>>(x, b_enc, b_sh, w_sig, b_sig,
                                      b_r1, W_r2, b_r2, out, n);
}

// round 7
// speedup vs baseline: 1.6175x; 1.6175x over previous
#include <cuda_runtime.h>
#include <stdint.h>

#define NTH  512
#define TP   64
#define WDIM 128
#define HDIM 64
#define EXP  8
#define DXX  63
#define DVV  27
#define KK1  78       // k-pairs for W_r1 (155 -> 156 padded)

typedef unsigned long long ull;

// ---- pre-packed weight scratch: [..][kp][c][2] (k-pair innermost) ----
__device__ float g_Wenc[32 * 128 * 2];
__device__ float g_Wsh [8 * 64 * 128 * 2];
__device__ float g_Wr1 [8 * KK1 * 64 * 2];

// ---- shared memory (ull-based transposed-pair arrays + float tail) ----
// y_tp  [64 kp][65] ull   (h[64][66] floats overlays after expert loop)
// shb   [64 kp][65] ull
// x_tp  [32 kp][65] ull
// vd_tp [14 kp][65] ull
#define U_Y    0
#define U_SHB  (U_Y   + 64*65)
#define U_X    (U_SHB + 64*65)
#define U_VD   (U_X   + 32*65)
#define U_END  (U_VD  + 14*65)
#define F_G    (U_END*2)            // [512]
#define F_RED  (F_G   + 512)        // [16][64]
#define F_BSC  (F_RED + 1024)       // [64]
#define F_BSIG (F_BSC + 64)
#define F_BEXP (F_BSIG + 64)
#define F_UPD  (F_BEXP + 64)
#define SMEM_FLOATS (F_UPD + 64)    // 24412 floats = 97648 B

__device__ __forceinline__ void ffma2(ull& acc, ull a, ull b) {
    asm("fma.rn.f32x2 %0, %1, %2, %0;" : "+l"(acc) : "l"(a), "l"(b));
}
__device__ __forceinline__ float2 unpack2(ull v) {
    float2 f; asm("mov.b64 {%0, %1}, %2;" : "=f"(f.x), "=f"(f.y) : "l"(v)); return f;
}
__device__ __forceinline__ ull pack2(float a, float b) {
    ull r; asm("mov.b64 %0, {%1, %2};" : "=l"(r) : "f"(a), "f"(b)); return r;
}

// ---- JAX threefry2x32 (20 rounds) ----
__device__ __forceinline__ uint2 tf2x32(unsigned k0, unsigned k1, unsigned x0, unsigned x1) {
    unsigned ks2 = k0 ^ k1 ^ 0x1BD11BDAu;
    x0 += k0; x1 += k1;
#define TFR(r) { x0 += x1; x1 = (x1 << (r)) | (x1 >> (32 - (r))); x1 ^= x0; }
    TFR(13) TFR(15) TFR(26) TFR(6)
    x0 += k1;  x1 += ks2 + 1u;
    TFR(17) TFR(29) TFR(16) TFR(24)
    x0 += ks2; x1 += k0 + 2u;
    TFR(13) TFR(15) TFR(26) TFR(6)
    x0 += k0;  x1 += k1 + 3u;
    TFR(17) TFR(29) TFR(16) TFR(24)
    x0 += k1;  x1 += ks2 + 4u;
    TFR(13) TFR(15) TFR(26) TFR(6)
    x0 += ks2; x1 += k0 + 5u;
#undef TFR
    return make_uint2(x0, x1);
}

__global__ void prep_pack(const float* __restrict__ W_enc,
                          const float* __restrict__ W_sh,
                          const float* __restrict__ W_r1) {
    const int i = blockIdx.x * blockDim.x + threadIdx.x;
    if (i < 32 * 128 * 2) {
        const int j = i & 1, c = (i >> 1) & 127, kp = i >> 8;
        const int k = 2 * kp + j;
        g_Wenc[i] = (k < DXX) ? W_enc[k * 128 + c] : 0.f;
    }
    const int i2 = i - 32 * 128 * 2;
    if (i2 >= 0 && i2 < 8 * 64 * 128 * 2) {
        const int j = i2 & 1, c = (i2 >> 1) & 127, kp = (i2 >> 8) & 63, e = i2 >> 14;
        g_Wsh[i2] = W_sh[e * 16384 + (2 * kp + j) * 128 + c];
    }
    const int i3 = i - (32 * 128 * 2 + 8 * 64 * 128 * 2);
    if (i3 >= 0 && i3 < 8 * KK1 * 64 * 2) {
        const int e = i3 / (KK1 * 64 * 2), r = i3 % (KK1 * 64 * 2);
        const int kp = r >> 7, c = (r >> 1) & 63, j = r & 1;
        const int k = 2 * kp + j;
        g_Wr1[i3] = (k < 155) ? W_r1[e * 155 * 64 + k * 64 + c] : 0.f;
    }
}

__global__ void __launch_bounds__(NTH, 1)
nerf_fused(const float* __restrict__ x,
           const float* __restrict__ b_enc,
           const float* __restrict__ b_sh,
           const float* __restrict__ w_sig, const float* __restrict__ b_sig,
           const float* __restrict__ b_r1,
           const float* __restrict__ W_r2,  const float* __restrict__ b_r2,
           float* __restrict__ out, int n)
{
    extern __shared__ float smf[];
    ull* sm8 = (ull*)smf;
    ull* y_tp  = sm8 + U_Y;
    ull* shb   = sm8 + U_SHB;
    ull* x_tp  = sm8 + U_X;
    ull* vd_tp = sm8 + U_VD;
    float* s_g    = smf + F_G;
    float* s_red  = smf + F_RED;
    float* s_bsc  = smf + F_BSC;
    float* s_bsig = smf + F_BSIG;
    float* s_bexp = smf + F_BEXP;
    float* s_upd  = smf + F_UPD;
    float* s_h    = (float*)y_tp;   // overlay: [64][66], used after expert loop

    const int tid = threadIdx.x;
    const int n0  = blockIdx.x * TP;
    const int wp  = tid >> 5, l = tid & 31;

    // ---------- Phase A: positional encodings into transposed-pair layouts ----------
    if (tid < 192) {
        const int p = tid / 3, c = tid % 3;
        float xc = 0.f, vc = 0.f;
        if (n0 + p < n) {
            xc = x[(n0 + p) * 6 + c];
            vc = x[(n0 + p) * 6 + 3 + c];
        }
        float* xf = (float*)x_tp;
        float* vf = (float*)vd_tp;
        // element k of point p lives at (k>>1)*130 + 2*p + (k&1)
#define PUTX(k, v) xf[((k) >> 1) * 130 + 2 * p + ((k) & 1)] = (v)
#define PUTV(k, v) vf[((k) >> 1) * 130 + 2 * p + ((k) & 1)] = (v)
        PUTX(c, xc);
        float f = 1.f;
#pragma unroll
        for (int i = 0; i < 10; i++) {
            float sv, cv; sincosf(f * xc, &sv, &cv);
            PUTX(3 + 3 * i + c, sv);
            PUTX(33 + 3 * i + c, cv);
            f *= 2.f;
        }
        PUTV(c, vc);
        f = 1.f;
#pragma unroll
        for (int i = 0; i < 4; i++) {
            float sv, cv; sincosf(f * vc, &sv, &cv);
            PUTV(3 + 3 * i + c, sv);
            PUTV(15 + 3 * i + c, cv);
            f *= 2.f;
        }
#undef PUTX
#undef PUTV
    }
    if (tid < 64) {
        ((float*)x_tp)[31 * 130 + 2 * tid + 1] = 0.f;   // x pad k=63
        ((float*)vd_tp)[13 * 130 + 2 * tid + 1] = 0.f;  // vd pad k=27
    }
    // ---------- Phase A2: Gumbel noise (JAX threefry, partitionable) ----------
    {
        const int p = tid >> 3;
        const unsigned f = (unsigned)(n0 + p) * 8u + (unsigned)(tid & 7);
        const uint2 r = tf2x32(0u, 42u, 0u, f);
        const unsigned bits = r.x ^ r.y;
        const float u = __uint_as_float((bits >> 9) | 0x3f800000u) - 1.0f;
        s_g[tid] = -logf(-logf(u + 1e-20f) + 1e-20f);
    }
    __syncthreads();

    // ---------- Phase B: y = relu(pe(x) @ W_enc + b), lane=point, warp=8 cols ----------
    {
        ull acc[8][2];
#pragma unroll
        for (int c = 0; c < 8; c++) { acc[c][0] = 0ull; acc[c][1] = 0ull; }
        const ulonglong2* wB = (const ulonglong2*)g_Wenc + wp * 4;
#pragma unroll 2
        for (int kp = 0; kp < 32; kp++) {
            const ull a0 = x_tp[kp * 65 + l];
            const ull a1 = x_tp[kp * 65 + 32 + l];
            const ulonglong2 q0 = wB[kp * 64 + 0], q1 = wB[kp * 64 + 1];
            const ulonglong2 q2 = wB[kp * 64 + 2], q3 = wB[kp * 64 + 3];
            ffma2(acc[0][0], a0, q0.x); ffma2(acc[0][1], a1, q0.x);
            ffma2(acc[1][0], a0, q0.y); ffma2(acc[1][1], a1, q0.y);
            ffma2(acc[2][0], a0, q1.x); ffma2(acc[2][1], a1, q1.x);
            ffma2(acc[3][0], a0, q1.y); ffma2(acc[3][1], a1, q1.y);
            ffma2(acc[4][0], a0, q2.x); ffma2(acc[4][1], a1, q2.x);
            ffma2(acc[5][0], a0, q2.y); ffma2(acc[5][1], a1, q2.y);
            ffma2(acc[6][0], a0, q3.x); ffma2(acc[6][1], a1, q3.x);
            ffma2(acc[7][0], a0, q3.y); ffma2(acc[7][1], a1, q3.y);
        }
        float v[8][2];
#pragma unroll
        for (int c = 0; c < 8; c++) {
            const float bc = b_enc[wp * 8 + c];
            const float2 f0 = unpack2(acc[c][0]), f1 = unpack2(acc[c][1]);
            v[c][0] = fmaxf(f0.x + f0.y + bc, 0.f);
            v[c][1] = fmaxf(f1.x + f1.y + bc, 0.f);
        }
#pragma unroll
        for (int h = 0; h < 2; h++)
#pragma unroll
            for (int j = 0; j < 4; j++)
                y_tp[(wp * 4 + j) * 65 + h * 32 + l] = pack2(v[2 * j][h], v[2 * j + 1][h]);
    }
    __syncthreads();

    // preload sigma weights for this warp's columns (uniform)
    float ws[8];
#pragma unroll
    for (int c = 0; c < 8; c++) ws[c] = w_sig[wp * 8 + c];

    // ---------- Expert loop: shape (regs) + sigma + gating; winners -> shb ----------
    for (int e = 0; e < EXP; e++) {
        ull acc[8][2];
#pragma unroll
        for (int c = 0; c < 8; c++) { acc[c][0] = 0ull; acc[c][1] = 0ull; }
        const ulonglong2* wS = (const ulonglong2*)(g_Wsh + e * 16384) + wp * 4;
#pragma unroll 2
        for (int kp = 0; kp < 64; kp++) {
            const ull a0 = y_tp[kp * 65 + l];
            const ull a1 = y_tp[kp * 65 + 32 + l];
            const ulonglong2 q0 = wS[kp * 64 + 0], q1 = wS[kp * 64 + 1];
            const ulonglong2 q2 = wS[kp * 64 + 2], q3 = wS[kp * 64 + 3];
            ffma2(acc[0][0], a0, q0.x); ffma2(acc[0][1], a1, q0.x);
            ffma2(acc[1][0], a0, q0.y); ffma2(acc[1][1], a1, q0.y);
            ffma2(acc[2][0], a0, q1.x); ffma2(acc[2][1], a1, q1.x);
            ffma2(acc[3][0], a0, q1.y); ffma2(acc[3][1], a1, q1.y);
            ffma2(acc[4][0], a0, q2.x); ffma2(acc[4][1], a1, q2.x);
            ffma2(acc[5][0], a0, q2.y); ffma2(acc[5][1], a1, q2.y);
            ffma2(acc[6][0], a0, q3.x); ffma2(acc[6][1], a1, q3.x);
            ffma2(acc[7][0], a0, q3.y); ffma2(acc[7][1], a1, q3.y);
        }
        float v[8][2];
        float sp0 = 0.f, sp1 = 0.f;
#pragma unroll
        for (int c = 0; c < 8; c++) {
            const float bc = b_sh[e * 128 + wp * 8 + c];
            const float2 f0 = unpack2(acc[c][0]), f1 = unpack2(acc[c][1]);
            v[c][0] = fmaxf(f0.x + f0.y + bc, 0.f);
            v[c][1] = fmaxf(f1.x + f1.y + bc, 0.f);
            sp0 = fmaf(v[c][0], ws[c], sp0);
            sp1 = fmaf(v[c][1], ws[c], sp1);
        }
        s_red[wp * 64 + l]      = sp0;
        s_red[wp * 64 + 32 + l] = sp1;
        __syncthreads();

        if (tid < 64) {
            float t = b_sig[0];
#pragma unroll
            for (int j = 0; j < 16; j++) t += s_red[j * 64 + tid];
            const float sg = fmaxf(t, 0.f) + log1pf(expf(-fabsf(t)));  // softplus
            const float sc = logf(sg + 1e-10f) / 0.166667f + s_g[tid * 8 + e];
            const bool win = (e == 0) || (sc > s_bsc[tid]);
            s_upd[tid] = win ? 1.f : 0.f;
            if (win) {
                s_bsc[tid]  = sc;
                s_bsig[tid] = sg;
                s_bexp[tid] = (float)e;
            }
        }
        __syncthreads();

        // conditional store of winning shape rows (straight from registers)
#pragma unroll
        for (int h = 0; h < 2; h++) {
            if (s_upd[h * 32 + l] != 0.f) {
#pragma unroll
                for (int j = 0; j < 4; j++)
                    shb[(wp * 4 + j) * 65 + h * 32 + l] = pack2(v[2 * j][h], v[2 * j + 1][h]);
            }
        }
        __syncthreads();
    }

    // ---------- C3': h = relu([shape | vd] @ W_r1[winner] + b), 16 warps x 4 pts ----------
    {
        const int p0 = wp * 4;
        int we[4];
        const ulonglong2* w1[4];
        ull acc[4][2];
#pragma unroll
        for (int p = 0; p < 4; p++) {
            we[p] = (int)s_bexp[p0 + p];
            w1[p] = (const ulonglong2*)(g_Wr1 + we[p] * (KK1 * 128)) + l;
            acc[p][0] = 0ull; acc[p][1] = 0ull;
        }
#pragma unroll 2
        for (int kp = 0; kp < 64; kp++) {
#pragma unroll
            for (int p = 0; p < 4; p++) {
                const ulonglong2 q = w1[p][kp * 32];
                const ull a = shb[kp * 65 + p0 + p];
                ffma2(acc[p][0], a, q.x);
                ffma2(acc[p][1], a, q.y);
            }
        }
#pragma unroll
        for (int kp = 64; kp < KK1; kp++) {
#pragma unroll
            for (int p = 0; p < 4; p++) {
                const ulonglong2 q = w1[p][kp * 32];
                const ull a = vd_tp[(kp - 64) * 65 + p0 + p];
                ffma2(acc[p][0], a, q.x);
                ffma2(acc[p][1], a, q.y);
            }
        }
        __syncthreads();   // all reads of the U_Y region done before s_h overlay writes
#pragma unroll
        for (int p = 0; p < 4; p++) {
            const float2 bv = *(const float2*)(b_r1 + we[p] * HDIM + l * 2);
            const float2 f0 = unpack2(acc[p][0]), f1 = unpack2(acc[p][1]);
            const float h0 = fmaxf(f0.x + f0.y + bv.x, 0.f);
            const float h1 = fmaxf(f1.x + f1.y + bv.y, 0.f);
            *(ull*)(s_h + (p0 + p) * 66 + l * 2) = pack2(h0, h1);
        }
    }
    __syncthreads();

    // ---------- C4': rgb = sigmoid(h @ W_r2[winner] + b) -> out ----------
    if (tid < 192) {
        const int p = tid % 64, c = tid / 64;
        const int we = (int)s_bexp[p];
        float acc = b_r2[we * 3 + c];
        const float* hp = s_h + p * 66;
        const float* w2 = W_r2 + we * HDIM * 3 + c;
#pragma unroll
        for (int k = 0; k < HDIM; k++) acc = fmaf(hp[k], w2[k * 3], acc);
        if (n0 + p < n)
            out[(n0 + p) * 4 + c] = 1.f / (1.f + expf(-acc));
    }
    if (tid < 64 && n0 + tid < n)
        out[(n0 + tid) * 4 + 3] = s_bsig[tid];
}

extern "C" void kernel_launch(void* const* d_in, const int* in_sizes, int n_in,
                              void* d_out, int out_size) {
    const float* x     = (const float*)d_in[0];
    const float* W_enc = (const float*)d_in[1];
    const float* b_enc = (const float*)d_in[2];
    const float* W_sh  = (const float*)d_in[3];
    const float* b_sh  = (const float*)d_in[4];
    const float* w_sig = (const float*)d_in[5];
    const float* b_sig = (const float*)d_in[6];
    const float* W_r1  = (const float*)d_in[7];
    const float* b_r1  = (const float*)d_in[8];
    const float* W_r2  = (const float*)d_in[9];
    const float* b_r2  = (const float*)d_in[10];
    float* out = (float*)d_out;

    const int n = in_sizes[0] / 6;
    const int blocks = (n + TP - 1) / TP;
    const int smem = SMEM_FLOATS * (int)sizeof(float);

    const int prep_elems = 32*128*2 + 8*64*128*2 + 8*KK1*64*2;
    prep_pack<<<(prep_elems + 255) / 256, 256>>>(W_enc, W_sh, W_r1);

    cudaFuncSetAttribute(nerf_fused, cudaFuncAttributeMaxDynamicSharedMemorySize, smem);
    nerf_fused<<<blocks, NTH, smem>>>(x, b_enc, b_sh, w_sig, b_sig,
                                      b_r1, W_r2, b_r2, out, n);
}